// round 8
// baseline (speedup 1.0000x reference)
#include <cuda_runtime.h>

// R8: third submission of the R6 kernel (two infra-flake retries).
// float4 gather + smem broadcast agg; CSR build trimmed to 3 launches.

#define N_MAX 100000
#define E_MAX 1600000

// ---------------- scratch (static device arrays; no allocation) ----------------
__device__ float g_h  [(size_t)N_MAX * 96];   // per-layer node features h = x @ W
__device__ float g_out[(size_t)N_MAX * 96];   // GAT aggregation output
__device__ float g_y  [(size_t)N_MAX * 32];   // reshape(3,N,32).sum(0) result
__device__ float g_s  [N_MAX];                // h @ a_src
__device__ float g_d  [N_MAX];                // h @ a_dst
__device__ int   g_rowptr[N_MAX + 1];
__device__ int   g_cnt[N_MAX];                // zero-init; invariant: zero at call entry
__device__ int   g_col[E_MAX];

// ---------------- CSR build ----------------
__global__ void k_zero_cnt(int Nn) {
    int i = blockIdx.x * blockDim.x + threadIdx.x;
    if (i < Nn) g_cnt[i] = 0;
}

__global__ void k_hist(const int* __restrict__ ei, int E, int Nn) {
    for (int e = blockIdx.x * blockDim.x + threadIdx.x; e < E; e += gridDim.x * blockDim.x) {
        int dd = ei[E + e];
        if ((unsigned)dd < (unsigned)Nn) atomicAdd(&g_cnt[dd], 1);
    }
}

// prefix-sum of g_cnt into g_rowptr; also re-zeros g_cnt for k_scatter
__global__ void k_scan(int Nn) {
    __shared__ int sm[1024];
    int t = threadIdx.x;
    int C = (Nn + 1023) >> 10;
    int b = t * C;
    int e = b + C; if (e > Nn) e = Nn;
    if (b > Nn) b = Nn;
    int sum = 0;
    for (int i = b; i < e; i++) sum += g_cnt[i];
    sm[t] = sum;
    __syncthreads();
    for (int off = 1; off < 1024; off <<= 1) {
        int v = (t >= off) ? sm[t - off] : 0;
        __syncthreads();
        sm[t] += v;
        __syncthreads();
    }
    int run = sm[t] - sum;  // exclusive prefix
    for (int i = b; i < e; i++) {
        g_rowptr[i] = run;
        run += g_cnt[i];
        g_cnt[i] = 0;                 // re-zero for scatter
    }
    if (t == 1023) g_rowptr[Nn] = sm[1023];
}

__global__ void k_scatter(const int* __restrict__ ei, int E, int Nn) {
    for (int e = blockIdx.x * blockDim.x + threadIdx.x; e < E; e += gridDim.x * blockDim.x) {
        int ss = ei[e];
        int dd = ei[E + e];
        if ((unsigned)dd < (unsigned)Nn) {
            int pos = g_rowptr[dd] + atomicAdd(&g_cnt[dd], 1);
            g_col[pos] = ss;
        }
    }
}

// ---------------- register-tiled GEMM: C[M,BN] = A[M,K] @ B[K,BN] (+bias, act) ----------------
// ACT: 0 = none, 1 = relu, 2 = sigmoid
template <int BN, int TN, int ACT>
__global__ void __launch_bounds__(256) k_gemm(const float* __restrict__ A,
                                              const float* __restrict__ B,
                                              const float* __restrict__ bias,
                                              float* __restrict__ C,
                                              int M, int K) {
    constexpr int BM = 128, BK = 32, TM = 8;
    constexpr int TX = BN / TN;          // 16
    __shared__ float As[BM][BK + 1];
    __shared__ float Bs[BK][BN + 1];
    int tid = threadIdx.x;
    int tx = tid % TX, ty = tid / TX;
    int row0 = blockIdx.x * BM;

    float acc[TM][TN];
#pragma unroll
    for (int r = 0; r < TM; r++)
#pragma unroll
        for (int c = 0; c < TN; c++) acc[r][c] = 0.f;

    for (int k0 = 0; k0 < K; k0 += BK) {
        for (int i = tid; i < BM * (BK / 4); i += 256) {
            int r = i >> 3;
            int c4 = i & 7;
            int gr = row0 + r;
            float4 v = make_float4(0.f, 0.f, 0.f, 0.f);
            if (gr < M) v = *(const float4*)&A[(size_t)gr * K + k0 + (c4 << 2)];
            As[r][(c4 << 2) + 0] = v.x;
            As[r][(c4 << 2) + 1] = v.y;
            As[r][(c4 << 2) + 2] = v.z;
            As[r][(c4 << 2) + 3] = v.w;
        }
        for (int i = tid; i < BK * (BN / 4); i += 256) {
            int r = i / (BN / 4);
            int c4 = i % (BN / 4);
            float4 v = *(const float4*)&B[(size_t)(k0 + r) * BN + (c4 << 2)];
            Bs[r][(c4 << 2) + 0] = v.x;
            Bs[r][(c4 << 2) + 1] = v.y;
            Bs[r][(c4 << 2) + 2] = v.z;
            Bs[r][(c4 << 2) + 3] = v.w;
        }
        __syncthreads();
#pragma unroll
        for (int kk = 0; kk < BK; kk++) {
            float a[TM], bb[TN];
#pragma unroll
            for (int r = 0; r < TM; r++) a[r] = As[ty * TM + r][kk];
#pragma unroll
            for (int c = 0; c < TN; c++) bb[c] = Bs[kk][tx * TN + c];
#pragma unroll
            for (int r = 0; r < TM; r++)
#pragma unroll
                for (int c = 0; c < TN; c++) acc[r][c] += a[r] * bb[c];
        }
        __syncthreads();
    }

#pragma unroll
    for (int r = 0; r < TM; r++) {
        int gr = row0 + ty * TM + r;
        if (gr < M) {
#pragma unroll
            for (int c = 0; c < TN; c++) {
                int col = tx * TN + c;
                float v = acc[r][c];
                if (bias) v += bias[col];
                if (ACT == 1) v = fmaxf(v, 0.f);
                if (ACT == 2) v = 1.f / (1.f + __expf(-v));
                C[(size_t)gr * BN + col] = v;
            }
        }
    }
}

// ---------------- s = h @ a_src, d = h @ a_dst (warp per node) ----------------
__global__ void k_sd(const float* __restrict__ h, const float* __restrict__ as_,
                     const float* __restrict__ ad_, int Nn) {
    int w = (int)((blockIdx.x * blockDim.x + threadIdx.x) >> 5);
    int lane = threadIdx.x & 31;
    if (w >= Nn) return;
    const float* hr = h + (size_t)w * 96;
    float s = 0.f, d = 0.f;
#pragma unroll
    for (int u = 0; u < 3; u++) {
        float hv = hr[lane + 32 * u];
        s += hv * as_[lane + 32 * u];
        d += hv * ad_[lane + 32 * u];
    }
#pragma unroll
    for (int off = 16; off; off >>= 1) {
        s += __shfl_xor_sync(0xffffffffu, s, off);
        d += __shfl_xor_sync(0xffffffffu, d, off);
    }
    if (lane == 0) { g_s[w] = s; g_d[w] = d; }
}

// ---------------- GAT softmax-aggregate (warp per dst node, float4 gather) ----------------
__device__ __forceinline__ float lrelu(float x) { return x > 0.f ? x : 0.2f * x; }

__global__ void __launch_bounds__(256) k_agg(const float* __restrict__ h,
                                             const float* __restrict__ bias,
                                             float* __restrict__ out, int Nn) {
    __shared__ float2 buf[8][32];
    int warp = threadIdx.x >> 5;
    int lane = threadIdx.x & 31;
    int n = blockIdx.x * 8 + warp;
    if (n >= Nn) return;                       // warp-uniform exit
    int beg = g_rowptr[n];
    int end = g_rowptr[n + 1];
    float dn = g_d[n];
    float e_self = lrelu(g_s[n] + dn);

    // pass 1: pure max
    float m = e_self;
    for (int j = beg + lane; j < end; j += 32)
        m = fmaxf(m, lrelu(g_s[g_col[j]] + dn));
#pragma unroll
    for (int off = 16; off; off >>= 1)
        m = fmaxf(m, __shfl_xor_sync(0xffffffffu, m, off));

    // pass 2: chunked exp + smem-broadcast float4 accumulate (lanes 0-23 active)
    float w_self = __expf(e_self - m);
    float p = (lane == 0) ? w_self : 0.f;
    bool act = lane < 24;
    float4 acc = make_float4(0.f, 0.f, 0.f, 0.f);
    if (act) {
        float4 hv = *(const float4*)&h[(size_t)n * 96 + lane * 4];
        acc.x = w_self * hv.x; acc.y = w_self * hv.y;
        acc.z = w_self * hv.z; acc.w = w_self * hv.w;
    }
    for (int j0 = beg; j0 < end; j0 += 32) {
        int j = j0 + lane;
        int c = 0; float w = 0.f;
        if (j < end) {
            c = g_col[j];
            w = __expf(lrelu(g_s[c] + dn) - m);
            p += w;
        }
        buf[warp][lane] = make_float2(__int_as_float(c), w);
        __syncwarp();
        int cnt = end - j0; if (cnt > 32) cnt = 32;
        if (act) {
            for (int t = 0; t < cnt; t++) {
                float2 cw = buf[warp][t];          // LDS.64 broadcast
                int   ct = __float_as_int(cw.x);
                float wt = cw.y;
                float4 hv = *(const float4*)&h[(size_t)ct * 96 + lane * 4];
                acc.x += wt * hv.x; acc.y += wt * hv.y;
                acc.z += wt * hv.z; acc.w += wt * hv.w;
            }
        }
        __syncwarp();
    }
#pragma unroll
    for (int off = 16; off; off >>= 1)
        p += __shfl_xor_sync(0xffffffffu, p, off);

    float scale = 1.f / (fmaxf(p, 1e-16f) * (float)(end - beg + 1));
    if (act) {
        const float4 bv = *(const float4*)&bias[lane * 4];
        float4 o4;
        o4.x = acc.x * scale + bv.x;
        o4.y = acc.y * scale + bv.y;
        o4.z = acc.z * scale + bv.z;
        o4.w = acc.w * scale + bv.w;
        *(float4*)&out[(size_t)n * 96 + lane * 4] = o4;
    }
}

// ---------------- faithful view(3,N,32).sum(0) [+relu] ----------------
__global__ void k_reshape(const float* __restrict__ src, float* __restrict__ dst,
                          int Nn, int doRelu) {
    int t = blockIdx.x * blockDim.x + threadIdx.x;
    int tot = Nn * 32;
    if (t >= tot) return;
    float v = src[t] + src[t + tot] + src[t + 2 * tot];
    if (doRelu) v = fmaxf(v, 0.f);
    dst[t] = v;
}

// ---------------- launch ----------------
extern "C" void kernel_launch(void* const* d_in, const int* in_sizes, int n_in,
                              void* d_out, int out_size) {
    const float* x   = (const float*)d_in[0];
    const int*   ei  = (const int*)d_in[1];          // int64 in ref -> int32 in harness
    const float* W1  = (const float*)d_in[2];
    const float* as1 = (const float*)d_in[3];
    const float* ad1 = (const float*)d_in[4];
    const float* b1  = (const float*)d_in[5];
    const float* W2  = (const float*)d_in[6];
    const float* as2 = (const float*)d_in[7];
    const float* ad2 = (const float*)d_in[8];
    const float* b2  = (const float*)d_in[9];
    const float* Wl1 = (const float*)d_in[12];
    const float* bl1 = (const float*)d_in[13];
    const float* Wl2 = (const float*)d_in[14];
    const float* bl2 = (const float*)d_in[15];
    float* out = (float*)d_out;

    int Nn = in_sizes[0] / 128;
    int E  = in_sizes[1] / 2;
    if (Nn > N_MAX) Nn = N_MAX;
    if (E  > E_MAX) E  = E_MAX;

    float *p_h, *p_out, *p_y;
    cudaGetSymbolAddress((void**)&p_h,   g_h);
    cudaGetSymbolAddress((void**)&p_out, g_out);
    cudaGetSymbolAddress((void**)&p_y,   g_y);

    int gb = (Nn + 127) / 128;
    int wb = (Nn + 7) / 8;            // warp-per-node kernels, 8 warps/block
    int rb = (Nn * 32 + 255) / 256;

    // ---- CSR build (g_cnt is zero at entry: static init / trailing zero) ----
    k_hist<<<1024, 256>>>(ei, E, Nn);          // launch 1
    k_scan<<<1, 1024>>>(Nn);                   // launch 2 (re-zeros g_cnt)
    k_scatter<<<1024, 256>>>(ei, E, Nn);       // launch 3

    // ---- layer 1 ----
    k_gemm<96, 6, 0><<<gb, 256>>>(x, W1, nullptr, p_h, Nn, 128);   // launch 4
    k_sd<<<wb, 256>>>(p_h, as1, ad1, Nn);                          // launch 5
    k_agg<<<wb, 256>>>(p_h, b1, p_out, Nn);                        // launch 6
    k_reshape<<<rb, 256>>>(p_out, p_y, Nn, 1);

    // ---- layer 2 ----
    k_gemm<96, 6, 0><<<gb, 256>>>(p_y, W2, nullptr, p_h, Nn, 32);
    k_sd<<<wb, 256>>>(p_h, as2, ad2, Nn);
    k_agg<<<wb, 256>>>(p_h, b2, p_out, Nn);
    k_reshape<<<rb, 256>>>(p_out, p_y, Nn, 0);

    // ---- MLP head ----
    k_gemm<96, 6, 1><<<gb, 256>>>(p_y, Wl1, bl1, p_h, Nn, 32);
    k_gemm<32, 2, 2><<<gb, 256>>>(p_h, Wl2, bl2, out, Nn, 96);

    // restore invariant: g_cnt == 0 for next call
    k_zero_cnt<<<(Nn + 255) / 256, 256>>>(Nn);

    (void)n_in; (void)out_size;
}

// round 9
// speedup vs baseline: 1.0800x; 1.0800x over previous
#include <cuda_runtime.h>

// R9: GEMM smem vectorization (LDS 14->5 per kk) + k_sd fused into GEMM epilogue.

#define N_MAX 100000
#define E_MAX 1600000

__device__ float g_h  [(size_t)N_MAX * 96];
__device__ float g_out[(size_t)N_MAX * 96];
__device__ float g_y  [(size_t)N_MAX * 32];
__device__ float g_s  [N_MAX];
__device__ float g_d  [N_MAX];
__device__ int   g_rowptr[N_MAX + 1];
__device__ int   g_cnt[N_MAX];                // zero-init; invariant: zero at call entry
__device__ int   g_col[E_MAX];

// ---------------- CSR build ----------------
__global__ void k_zero_cnt(int Nn) {
    int i = blockIdx.x * blockDim.x + threadIdx.x;
    if (i < Nn) g_cnt[i] = 0;
}

__global__ void k_hist(const int* __restrict__ ei, int E, int Nn) {
    for (int e = blockIdx.x * blockDim.x + threadIdx.x; e < E; e += gridDim.x * blockDim.x) {
        int dd = ei[E + e];
        if ((unsigned)dd < (unsigned)Nn) atomicAdd(&g_cnt[dd], 1);
    }
}

__global__ void k_scan(int Nn) {
    __shared__ int sm[1024];
    int t = threadIdx.x;
    int C = (Nn + 1023) >> 10;
    int b = t * C;
    int e = b + C; if (e > Nn) e = Nn;
    if (b > Nn) b = Nn;
    int sum = 0;
    for (int i = b; i < e; i++) sum += g_cnt[i];
    sm[t] = sum;
    __syncthreads();
    for (int off = 1; off < 1024; off <<= 1) {
        int v = (t >= off) ? sm[t - off] : 0;
        __syncthreads();
        sm[t] += v;
        __syncthreads();
    }
    int run = sm[t] - sum;
    for (int i = b; i < e; i++) {
        g_rowptr[i] = run;
        run += g_cnt[i];
        g_cnt[i] = 0;                 // re-zero for scatter
    }
    if (t == 1023) g_rowptr[Nn] = sm[1023];
}

__global__ void k_scatter(const int* __restrict__ ei, int E, int Nn) {
    for (int e = blockIdx.x * blockDim.x + threadIdx.x; e < E; e += gridDim.x * blockDim.x) {
        int ss = ei[e];
        int dd = ei[E + e];
        if ((unsigned)dd < (unsigned)Nn) {
            int pos = g_rowptr[dd] + atomicAdd(&g_cnt[dd], 1);
            g_col[pos] = ss;
        }
    }
}

// ---------------- GEMM: C[M,BN] = A[M,K] @ B[K,BN], optional bias/act, optional fused s/d ----------------
// ACT: 0 none, 1 relu, 2 sigmoid.  SD: also emit g_s = C@a_s, g_d = C@a_d (pre-bias C).
template <int BN, int TN, int ACT, bool SD>
__global__ void __launch_bounds__(256) k_gemm(const float* __restrict__ A,
                                              const float* __restrict__ B,
                                              const float* __restrict__ bias,
                                              float* __restrict__ C,
                                              const float* __restrict__ av_s,
                                              const float* __restrict__ av_d,
                                              int M, int K) {
    constexpr int BM = 128, BK = 32, TM = 8;
    constexpr int TX = BN / TN;                 // 16
    __shared__ float Ast[BK][BM + 4];           // transposed A tile, pitch 132
    __shared__ float Bs[BK][BN + 2];            // pitch 98 (even, for LDS.64)
    int tid = threadIdx.x;
    int tx = tid % TX, ty = tid / TX;
    int row0 = blockIdx.x * BM;

    float acc[TM][TN];
#pragma unroll
    for (int r = 0; r < TM; r++)
#pragma unroll
        for (int c = 0; c < TN; c++) acc[r][c] = 0.f;

    for (int k0 = 0; k0 < K; k0 += BK) {
        // A tile (BM x BK) -> transposed smem
        for (int i = tid; i < BM * (BK / 4); i += 256) {
            int r = i >> 3;
            int c4 = i & 7;
            int gr = row0 + r;
            float4 v = make_float4(0.f, 0.f, 0.f, 0.f);
            if (gr < M) v = *(const float4*)&A[(size_t)gr * K + k0 + (c4 << 2)];
            Ast[(c4 << 2) + 0][r] = v.x;
            Ast[(c4 << 2) + 1][r] = v.y;
            Ast[(c4 << 2) + 2][r] = v.z;
            Ast[(c4 << 2) + 3][r] = v.w;
        }
        // B tile (BK x BN)
        for (int i = tid; i < BK * (BN / 4); i += 256) {
            int r = i / (BN / 4);
            int c4 = i % (BN / 4);
            float4 v = *(const float4*)&B[(size_t)(k0 + r) * BN + (c4 << 2)];
            *(float2*)&Bs[r][(c4 << 2)]     = make_float2(v.x, v.y);
            *(float2*)&Bs[r][(c4 << 2) + 2] = make_float2(v.z, v.w);
        }
        __syncthreads();
#pragma unroll 8
        for (int kk = 0; kk < BK; kk++) {
            float4 a0 = *(const float4*)&Ast[kk][ty * TM];        // LDS.128 broadcast
            float4 a1 = *(const float4*)&Ast[kk][ty * TM + 4];
            float a[TM] = {a0.x, a0.y, a0.z, a0.w, a1.x, a1.y, a1.z, a1.w};
            float bb[TN];
#pragma unroll
            for (int c2 = 0; c2 < TN / 2; c2++) {
                float2 t = *(const float2*)&Bs[kk][tx * TN + c2 * 2];  // LDS.64
                bb[c2 * 2]     = t.x;
                bb[c2 * 2 + 1] = t.y;
            }
#pragma unroll
            for (int r = 0; r < TM; r++)
#pragma unroll
                for (int c = 0; c < TN; c++) acc[r][c] += a[r] * bb[c];
        }
        __syncthreads();
    }

    if (SD) {
        float sp[TM], dp[TM];
#pragma unroll
        for (int r = 0; r < TM; r++) { sp[r] = 0.f; dp[r] = 0.f; }
#pragma unroll
        for (int c = 0; c < TN; c++) {
            int col = tx * TN + c;
            float asv = av_s[col];
            float adv = av_d[col];
#pragma unroll
            for (int r = 0; r < TM; r++) {
                sp[r] += acc[r][c] * asv;
                dp[r] += acc[r][c] * adv;
            }
        }
#pragma unroll
        for (int r = 0; r < TM; r++) {
#pragma unroll
            for (int off = 1; off < 16; off <<= 1) {   // reduce across tx (16-lane group)
                sp[r] += __shfl_xor_sync(0xffffffffu, sp[r], off);
                dp[r] += __shfl_xor_sync(0xffffffffu, dp[r], off);
            }
            int gr = row0 + ty * TM + r;
            if (tx == 0 && gr < M) {
                g_s[gr] = sp[r];
                g_d[gr] = dp[r];
            }
        }
    }

#pragma unroll
    for (int r = 0; r < TM; r++) {
        int gr = row0 + ty * TM + r;
        if (gr < M) {
#pragma unroll
            for (int c = 0; c < TN; c++) {
                int col = tx * TN + c;
                float v = acc[r][c];
                if (bias) v += bias[col];
                if (ACT == 1) v = fmaxf(v, 0.f);
                if (ACT == 2) v = 1.f / (1.f + __expf(-v));
                C[(size_t)gr * BN + col] = v;
            }
        }
    }
}

// ---------------- GAT softmax-aggregate (warp per dst node, float4 gather) ----------------
__device__ __forceinline__ float lrelu(float x) { return x > 0.f ? x : 0.2f * x; }

__global__ void __launch_bounds__(256) k_agg(const float* __restrict__ h,
                                             const float* __restrict__ bias,
                                             float* __restrict__ out, int Nn) {
    __shared__ float2 buf[8][32];
    int warp = threadIdx.x >> 5;
    int lane = threadIdx.x & 31;
    int n = blockIdx.x * 8 + warp;
    if (n >= Nn) return;
    int beg = g_rowptr[n];
    int end = g_rowptr[n + 1];
    float dn = g_d[n];
    float e_self = lrelu(g_s[n] + dn);

    // pass 1: pure max
    float m = e_self;
    for (int j = beg + lane; j < end; j += 32)
        m = fmaxf(m, lrelu(g_s[g_col[j]] + dn));
#pragma unroll
    for (int off = 16; off; off >>= 1)
        m = fmaxf(m, __shfl_xor_sync(0xffffffffu, m, off));

    // pass 2: chunked exp + smem-broadcast float4 accumulate (lanes 0-23 active)
    float w_self = __expf(e_self - m);
    float p = (lane == 0) ? w_self : 0.f;
    bool act = lane < 24;
    float4 acc = make_float4(0.f, 0.f, 0.f, 0.f);
    if (act) {
        float4 hv = *(const float4*)&h[(size_t)n * 96 + lane * 4];
        acc.x = w_self * hv.x; acc.y = w_self * hv.y;
        acc.z = w_self * hv.z; acc.w = w_self * hv.w;
    }
    for (int j0 = beg; j0 < end; j0 += 32) {
        int j = j0 + lane;
        int c = 0; float w = 0.f;
        if (j < end) {
            c = g_col[j];
            w = __expf(lrelu(g_s[c] + dn) - m);
            p += w;
        }
        buf[warp][lane] = make_float2(__int_as_float(c), w);
        __syncwarp();
        int cnt = end - j0; if (cnt > 32) cnt = 32;
        if (act) {
            for (int t = 0; t < cnt; t++) {
                float2 cw = buf[warp][t];
                int   ct = __float_as_int(cw.x);
                float wt = cw.y;
                float4 hv = *(const float4*)&h[(size_t)ct * 96 + lane * 4];
                acc.x += wt * hv.x; acc.y += wt * hv.y;
                acc.z += wt * hv.z; acc.w += wt * hv.w;
            }
        }
        __syncwarp();
    }
#pragma unroll
    for (int off = 16; off; off >>= 1)
        p += __shfl_xor_sync(0xffffffffu, p, off);

    float scale = 1.f / (fmaxf(p, 1e-16f) * (float)(end - beg + 1));
    if (act) {
        const float4 bv = *(const float4*)&bias[lane * 4];
        float4 o4;
        o4.x = acc.x * scale + bv.x;
        o4.y = acc.y * scale + bv.y;
        o4.z = acc.z * scale + bv.z;
        o4.w = acc.w * scale + bv.w;
        *(float4*)&out[(size_t)n * 96 + lane * 4] = o4;
    }
}

// ---------------- faithful view(3,N,32).sum(0) [+relu] ----------------
__global__ void k_reshape(const float* __restrict__ src, float* __restrict__ dst,
                          int Nn, int doRelu) {
    int t = blockIdx.x * blockDim.x + threadIdx.x;
    int tot = Nn * 32;
    if (t >= tot) return;
    float v = src[t] + src[t + tot] + src[t + 2 * tot];
    if (doRelu) v = fmaxf(v, 0.f);
    dst[t] = v;
}

// ---------------- launch ----------------
extern "C" void kernel_launch(void* const* d_in, const int* in_sizes, int n_in,
                              void* d_out, int out_size) {
    const float* x   = (const float*)d_in[0];
    const int*   ei  = (const int*)d_in[1];
    const float* W1  = (const float*)d_in[2];
    const float* as1 = (const float*)d_in[3];
    const float* ad1 = (const float*)d_in[4];
    const float* b1  = (const float*)d_in[5];
    const float* W2  = (const float*)d_in[6];
    const float* as2 = (const float*)d_in[7];
    const float* ad2 = (const float*)d_in[8];
    const float* b2  = (const float*)d_in[9];
    const float* Wl1 = (const float*)d_in[12];
    const float* bl1 = (const float*)d_in[13];
    const float* Wl2 = (const float*)d_in[14];
    const float* bl2 = (const float*)d_in[15];
    float* out = (float*)d_out;

    int Nn = in_sizes[0] / 128;
    int E  = in_sizes[1] / 2;
    if (Nn > N_MAX) Nn = N_MAX;
    if (E  > E_MAX) E  = E_MAX;

    float *p_h, *p_out, *p_y;
    cudaGetSymbolAddress((void**)&p_h,   g_h);
    cudaGetSymbolAddress((void**)&p_out, g_out);
    cudaGetSymbolAddress((void**)&p_y,   g_y);

    int gb = (Nn + 127) / 128;
    int wb = (Nn + 7) / 8;
    int rb = (Nn * 32 + 255) / 256;

    // ---- CSR build ----
    k_hist<<<1024, 256>>>(ei, E, Nn);                      // 1
    k_scan<<<1, 1024>>>(Nn);                               // 2
    k_scatter<<<1024, 256>>>(ei, E, Nn);                   // 3

    // ---- layer 1 (gemm computes h AND s/d) ----
    k_gemm<96, 6, 0, true><<<gb, 256>>>(x, W1, nullptr, p_h, as1, ad1, Nn, 128);  // 4
    k_agg<<<wb, 256>>>(p_h, b1, p_out, Nn);                // 5
    k_reshape<<<rb, 256>>>(p_out, p_y, Nn, 1);             // 6

    // ---- layer 2 ----
    k_gemm<96, 6, 0, true><<<gb, 256>>>(p_y, W2, nullptr, p_h, as2, ad2, Nn, 32);
    k_agg<<<wb, 256>>>(p_h, b2, p_out, Nn);
    k_reshape<<<rb, 256>>>(p_out, p_y, Nn, 0);

    // ---- MLP head ----
    k_gemm<96, 6, 1, false><<<gb, 256>>>(p_y, Wl1, bl1, p_h, nullptr, nullptr, Nn, 32);
    k_gemm<32, 2, 2, false><<<gb, 256>>>(p_h, Wl2, bl2, out, nullptr, nullptr, Nn, 96);

    // restore invariant: g_cnt == 0 for next call
    k_zero_cnt<<<(Nn + 255) / 256, 256>>>(Nn);

    (void)n_in; (void)out_size;
}

// round 10
// speedup vs baseline: 1.2319x; 1.1407x over previous
#include <cuda_runtime.h>

// R10: 4x unrolled agg gather (MLP 1->4) + vectorized scan.

#define N_MAX 100000
#define E_MAX 1600000

__device__ float g_h  [(size_t)N_MAX * 96];
__device__ float g_out[(size_t)N_MAX * 96];
__device__ float g_y  [(size_t)N_MAX * 32];
__device__ float g_s  [N_MAX];
__device__ float g_d  [N_MAX];
__device__ int   g_rowptr[N_MAX + 1];
__device__ int   g_cnt[N_MAX];                // zero-init; invariant: zero at call entry
__device__ int   g_col[E_MAX];

// ---------------- CSR build ----------------
__global__ void k_zero_cnt(int Nn) {
    int i = blockIdx.x * blockDim.x + threadIdx.x;
    if (i < Nn) g_cnt[i] = 0;
}

__global__ void k_hist(const int* __restrict__ ei, int E, int Nn) {
    for (int e = blockIdx.x * blockDim.x + threadIdx.x; e < E; e += gridDim.x * blockDim.x) {
        int dd = ei[E + e];
        if ((unsigned)dd < (unsigned)Nn) atomicAdd(&g_cnt[dd], 1);
    }
}

__global__ void k_scan(int Nn) {
    __shared__ int sm[1024];
    int t = threadIdx.x;
    int C = (Nn + 1023) >> 10;
    C = (C + 3) & ~3;                       // pad to multiple of 4 -> int4-aligned ranges
    int b = t * C;
    int e = b + C;
    if (b > Nn) b = Nn;
    if (e > Nn) e = Nn;
    int sum = 0;
    {
        int i = b;
        for (; i + 4 <= e; i += 4) {
            int4 v = *(const int4*)&g_cnt[i];
            sum += v.x + v.y + v.z + v.w;
        }
        for (; i < e; i++) sum += g_cnt[i];
    }
    sm[t] = sum;
    __syncthreads();
    for (int off = 1; off < 1024; off <<= 1) {
        int v = (t >= off) ? sm[t - off] : 0;
        __syncthreads();
        sm[t] += v;
        __syncthreads();
    }
    int run = sm[t] - sum;
    {
        int i = b;
        for (; i + 4 <= e; i += 4) {
            int4 v = *(const int4*)&g_cnt[i];
            g_rowptr[i]     = run;  run += v.x;
            g_rowptr[i + 1] = run;  run += v.y;
            g_rowptr[i + 2] = run;  run += v.z;
            g_rowptr[i + 3] = run;  run += v.w;
            *(int4*)&g_cnt[i] = make_int4(0, 0, 0, 0);   // re-zero for scatter
        }
        for (; i < e; i++) {
            g_rowptr[i] = run;
            run += g_cnt[i];
            g_cnt[i] = 0;
        }
    }
    if (t == 1023) g_rowptr[Nn] = sm[1023];
}

__global__ void k_scatter(const int* __restrict__ ei, int E, int Nn) {
    for (int e = blockIdx.x * blockDim.x + threadIdx.x; e < E; e += gridDim.x * blockDim.x) {
        int ss = ei[e];
        int dd = ei[E + e];
        if ((unsigned)dd < (unsigned)Nn) {
            int pos = g_rowptr[dd] + atomicAdd(&g_cnt[dd], 1);
            g_col[pos] = ss;
        }
    }
}

// ---------------- GEMM: C[M,BN] = A[M,K] @ B[K,BN], optional bias/act, optional fused s/d ----------------
template <int BN, int TN, int ACT, bool SD>
__global__ void __launch_bounds__(256) k_gemm(const float* __restrict__ A,
                                              const float* __restrict__ B,
                                              const float* __restrict__ bias,
                                              float* __restrict__ C,
                                              const float* __restrict__ av_s,
                                              const float* __restrict__ av_d,
                                              int M, int K) {
    constexpr int BM = 128, BK = 32, TM = 8;
    constexpr int TX = BN / TN;                 // 16
    __shared__ float Ast[BK][BM + 4];
    __shared__ float Bs[BK][BN + 2];
    int tid = threadIdx.x;
    int tx = tid % TX, ty = tid / TX;
    int row0 = blockIdx.x * BM;

    float acc[TM][TN];
#pragma unroll
    for (int r = 0; r < TM; r++)
#pragma unroll
        for (int c = 0; c < TN; c++) acc[r][c] = 0.f;

    for (int k0 = 0; k0 < K; k0 += BK) {
        for (int i = tid; i < BM * (BK / 4); i += 256) {
            int r = i >> 3;
            int c4 = i & 7;
            int gr = row0 + r;
            float4 v = make_float4(0.f, 0.f, 0.f, 0.f);
            if (gr < M) v = *(const float4*)&A[(size_t)gr * K + k0 + (c4 << 2)];
            Ast[(c4 << 2) + 0][r] = v.x;
            Ast[(c4 << 2) + 1][r] = v.y;
            Ast[(c4 << 2) + 2][r] = v.z;
            Ast[(c4 << 2) + 3][r] = v.w;
        }
        for (int i = tid; i < BK * (BN / 4); i += 256) {
            int r = i / (BN / 4);
            int c4 = i % (BN / 4);
            float4 v = *(const float4*)&B[(size_t)(k0 + r) * BN + (c4 << 2)];
            *(float2*)&Bs[r][(c4 << 2)]     = make_float2(v.x, v.y);
            *(float2*)&Bs[r][(c4 << 2) + 2] = make_float2(v.z, v.w);
        }
        __syncthreads();
#pragma unroll 8
        for (int kk = 0; kk < BK; kk++) {
            float4 a0 = *(const float4*)&Ast[kk][ty * TM];
            float4 a1 = *(const float4*)&Ast[kk][ty * TM + 4];
            float a[TM] = {a0.x, a0.y, a0.z, a0.w, a1.x, a1.y, a1.z, a1.w};
            float bb[TN];
#pragma unroll
            for (int c2 = 0; c2 < TN / 2; c2++) {
                float2 t = *(const float2*)&Bs[kk][tx * TN + c2 * 2];
                bb[c2 * 2]     = t.x;
                bb[c2 * 2 + 1] = t.y;
            }
#pragma unroll
            for (int r = 0; r < TM; r++)
#pragma unroll
                for (int c = 0; c < TN; c++) acc[r][c] += a[r] * bb[c];
        }
        __syncthreads();
    }

    if (SD) {
        float sp[TM], dp[TM];
#pragma unroll
        for (int r = 0; r < TM; r++) { sp[r] = 0.f; dp[r] = 0.f; }
#pragma unroll
        for (int c = 0; c < TN; c++) {
            int col = tx * TN + c;
            float asv = av_s[col];
            float adv = av_d[col];
#pragma unroll
            for (int r = 0; r < TM; r++) {
                sp[r] += acc[r][c] * asv;
                dp[r] += acc[r][c] * adv;
            }
        }
#pragma unroll
        for (int r = 0; r < TM; r++) {
#pragma unroll
            for (int off = 1; off < 16; off <<= 1) {
                sp[r] += __shfl_xor_sync(0xffffffffu, sp[r], off);
                dp[r] += __shfl_xor_sync(0xffffffffu, dp[r], off);
            }
            int gr = row0 + ty * TM + r;
            if (tx == 0 && gr < M) {
                g_s[gr] = sp[r];
                g_d[gr] = dp[r];
            }
        }
    }

#pragma unroll
    for (int r = 0; r < TM; r++) {
        int gr = row0 + ty * TM + r;
        if (gr < M) {
#pragma unroll
            for (int c = 0; c < TN; c++) {
                int col = tx * TN + c;
                float v = acc[r][c];
                if (bias) v += bias[col];
                if (ACT == 1) v = fmaxf(v, 0.f);
                if (ACT == 2) v = 1.f / (1.f + __expf(-v));
                C[(size_t)gr * BN + col] = v;
            }
        }
    }
}

// ---------------- GAT softmax-aggregate (warp per dst node, 4x-unrolled float4 gather) ----------------
__device__ __forceinline__ float lrelu(float x) { return x > 0.f ? x : 0.2f * x; }

__global__ void __launch_bounds__(256) k_agg(const float* __restrict__ h,
                                             const float* __restrict__ bias,
                                             float* __restrict__ out, int Nn) {
    __shared__ float2 buf[8][32];
    int warp = threadIdx.x >> 5;
    int lane = threadIdx.x & 31;
    int n = blockIdx.x * 8 + warp;
    if (n >= Nn) return;
    int beg = g_rowptr[n];
    int end = g_rowptr[n + 1];
    float dn = g_d[n];
    float e_self = lrelu(g_s[n] + dn);

    // pass 1: pure max
    float m = e_self;
    for (int j = beg + lane; j < end; j += 32)
        m = fmaxf(m, lrelu(g_s[g_col[j]] + dn));
#pragma unroll
    for (int off = 16; off; off >>= 1)
        m = fmaxf(m, __shfl_xor_sync(0xffffffffu, m, off));

    // pass 2: chunked exp + smem-broadcast float4 accumulate, 4x unrolled gather
    float w_self = __expf(e_self - m);
    float p = (lane == 0) ? w_self : 0.f;
    bool act = lane < 24;
    float4 acc = make_float4(0.f, 0.f, 0.f, 0.f);
    if (act) {
        float4 hv = *(const float4*)&h[(size_t)n * 96 + lane * 4];
        acc.x = w_self * hv.x; acc.y = w_self * hv.y;
        acc.z = w_self * hv.z; acc.w = w_self * hv.w;
    }
    for (int j0 = beg; j0 < end; j0 += 32) {
        int j = j0 + lane;
        int c = 0; float w = 0.f;
        if (j < end) {
            c = g_col[j];
            w = __expf(lrelu(g_s[c] + dn) - m);
            p += w;
        }
        buf[warp][lane] = make_float2(__int_as_float(c), w);
        __syncwarp();
        int cnt = end - j0; if (cnt > 32) cnt = 32;
        if (act) {
            const size_t lo = (size_t)lane * 4;
            int t = 0;
            for (; t + 4 <= cnt; t += 4) {
                float2 cw0 = buf[warp][t];
                float2 cw1 = buf[warp][t + 1];
                float2 cw2 = buf[warp][t + 2];
                float2 cw3 = buf[warp][t + 3];
                float4 h0 = *(const float4*)&h[(size_t)__float_as_int(cw0.x) * 96 + lo];
                float4 h1 = *(const float4*)&h[(size_t)__float_as_int(cw1.x) * 96 + lo];
                float4 h2 = *(const float4*)&h[(size_t)__float_as_int(cw2.x) * 96 + lo];
                float4 h3 = *(const float4*)&h[(size_t)__float_as_int(cw3.x) * 96 + lo];
                acc.x += cw0.y * h0.x; acc.y += cw0.y * h0.y; acc.z += cw0.y * h0.z; acc.w += cw0.y * h0.w;
                acc.x += cw1.y * h1.x; acc.y += cw1.y * h1.y; acc.z += cw1.y * h1.z; acc.w += cw1.y * h1.w;
                acc.x += cw2.y * h2.x; acc.y += cw2.y * h2.y; acc.z += cw2.y * h2.z; acc.w += cw2.y * h2.w;
                acc.x += cw3.y * h3.x; acc.y += cw3.y * h3.y; acc.z += cw3.y * h3.z; acc.w += cw3.y * h3.w;
            }
            for (; t < cnt; t++) {
                float2 cw = buf[warp][t];
                float4 hv = *(const float4*)&h[(size_t)__float_as_int(cw.x) * 96 + lo];
                acc.x += cw.y * hv.x; acc.y += cw.y * hv.y;
                acc.z += cw.y * hv.z; acc.w += cw.y * hv.w;
            }
        }
        __syncwarp();
    }
#pragma unroll
    for (int off = 16; off; off >>= 1)
        p += __shfl_xor_sync(0xffffffffu, p, off);

    float scale = 1.f / (fmaxf(p, 1e-16f) * (float)(end - beg + 1));
    if (act) {
        const float4 bv = *(const float4*)&bias[lane * 4];
        float4 o4;
        o4.x = acc.x * scale + bv.x;
        o4.y = acc.y * scale + bv.y;
        o4.z = acc.z * scale + bv.z;
        o4.w = acc.w * scale + bv.w;
        *(float4*)&out[(size_t)n * 96 + lane * 4] = o4;
    }
}

// ---------------- faithful view(3,N,32).sum(0) [+relu] ----------------
__global__ void k_reshape(const float* __restrict__ src, float* __restrict__ dst,
                          int Nn, int doRelu) {
    int t = blockIdx.x * blockDim.x + threadIdx.x;
    int tot = Nn * 32;
    if (t >= tot) return;
    float v = src[t] + src[t + tot] + src[t + 2 * tot];
    if (doRelu) v = fmaxf(v, 0.f);
    dst[t] = v;
}

// ---------------- launch ----------------
extern "C" void kernel_launch(void* const* d_in, const int* in_sizes, int n_in,
                              void* d_out, int out_size) {
    const float* x   = (const float*)d_in[0];
    const int*   ei  = (const int*)d_in[1];
    const float* W1  = (const float*)d_in[2];
    const float* as1 = (const float*)d_in[3];
    const float* ad1 = (const float*)d_in[4];
    const float* b1  = (const float*)d_in[5];
    const float* W2  = (const float*)d_in[6];
    const float* as2 = (const float*)d_in[7];
    const float* ad2 = (const float*)d_in[8];
    const float* b2  = (const float*)d_in[9];
    const float* Wl1 = (const float*)d_in[12];
    const float* bl1 = (const float*)d_in[13];
    const float* Wl2 = (const float*)d_in[14];
    const float* bl2 = (const float*)d_in[15];
    float* out = (float*)d_out;

    int Nn = in_sizes[0] / 128;
    int E  = in_sizes[1] / 2;
    if (Nn > N_MAX) Nn = N_MAX;
    if (E  > E_MAX) E  = E_MAX;

    float *p_h, *p_out, *p_y;
    cudaGetSymbolAddress((void**)&p_h,   g_h);
    cudaGetSymbolAddress((void**)&p_out, g_out);
    cudaGetSymbolAddress((void**)&p_y,   g_y);

    int gb = (Nn + 127) / 128;
    int wb = (Nn + 7) / 8;
    int rb = (Nn * 32 + 255) / 256;

    // ---- CSR build ----
    k_hist<<<1024, 256>>>(ei, E, Nn);                      // 1
    k_scan<<<1, 1024>>>(Nn);                               // 2
    k_scatter<<<1024, 256>>>(ei, E, Nn);                   // 3

    // ---- layer 1 (gemm computes h AND s/d) ----
    k_gemm<96, 6, 0, true><<<gb, 256>>>(x, W1, nullptr, p_h, as1, ad1, Nn, 128);  // 4 (profiled)
    k_agg<<<wb, 256>>>(p_h, b1, p_out, Nn);                // 5
    k_reshape<<<rb, 256>>>(p_out, p_y, Nn, 1);             // 6

    // ---- layer 2 ----
    k_gemm<96, 6, 0, true><<<gb, 256>>>(p_y, W2, nullptr, p_h, as2, ad2, Nn, 32);
    k_agg<<<wb, 256>>>(p_h, b2, p_out, Nn);
    k_reshape<<<rb, 256>>>(p_out, p_y, Nn, 0);

    // ---- MLP head ----
    k_gemm<96, 6, 1, false><<<gb, 256>>>(p_y, Wl1, bl1, p_h, nullptr, nullptr, Nn, 32);
    k_gemm<32, 2, 2, false><<<gb, 256>>>(p_h, Wl2, bl2, out, nullptr, nullptr, Nn, 96);

    // restore invariant: g_cnt == 0 for next call
    k_zero_cnt<<<(Nn + 255) / 256, 256>>>(Nn);

    (void)n_in; (void)out_size;
}

// round 13
// speedup vs baseline: 1.3031x; 1.0578x over previous
#include <cuda_runtime.h>

// R13: third submission of the R11 kernel (two infra flakes; R8 precedent).
// gemm __launch_bounds__(256,3); agg caches (s,col) in smem -> single gather pass.

#define N_MAX 100000
#define E_MAX 1600000

__device__ float g_h  [(size_t)N_MAX * 96];
__device__ float g_out[(size_t)N_MAX * 96];
__device__ float g_y  [(size_t)N_MAX * 32];
__device__ float g_s  [N_MAX];
__device__ float g_d  [N_MAX];
__device__ int   g_rowptr[N_MAX + 1];
__device__ int   g_cnt[N_MAX];                // zero-init; invariant: zero at call entry
__device__ int   g_col[E_MAX];

// ---------------- CSR build ----------------
__global__ void k_zero_cnt(int Nn) {
    int i = blockIdx.x * blockDim.x + threadIdx.x;
    if (i < Nn) g_cnt[i] = 0;
}

__global__ void k_hist(const int* __restrict__ ei, int E, int Nn) {
    for (int e = blockIdx.x * blockDim.x + threadIdx.x; e < E; e += gridDim.x * blockDim.x) {
        int dd = ei[E + e];
        if ((unsigned)dd < (unsigned)Nn) atomicAdd(&g_cnt[dd], 1);
    }
}

__global__ void k_scan(int Nn) {
    __shared__ int sm[1024];
    int t = threadIdx.x;
    int C = (Nn + 1023) >> 10;
    C = (C + 3) & ~3;
    int b = t * C;
    int e = b + C;
    if (b > Nn) b = Nn;
    if (e > Nn) e = Nn;
    int sum = 0;
    {
        int i = b;
        for (; i + 4 <= e; i += 4) {
            int4 v = *(const int4*)&g_cnt[i];
            sum += v.x + v.y + v.z + v.w;
        }
        for (; i < e; i++) sum += g_cnt[i];
    }
    sm[t] = sum;
    __syncthreads();
    for (int off = 1; off < 1024; off <<= 1) {
        int v = (t >= off) ? sm[t - off] : 0;
        __syncthreads();
        sm[t] += v;
        __syncthreads();
    }
    int run = sm[t] - sum;
    {
        int i = b;
        for (; i + 4 <= e; i += 4) {
            int4 v = *(const int4*)&g_cnt[i];
            g_rowptr[i]     = run;  run += v.x;
            g_rowptr[i + 1] = run;  run += v.y;
            g_rowptr[i + 2] = run;  run += v.z;
            g_rowptr[i + 3] = run;  run += v.w;
            *(int4*)&g_cnt[i] = make_int4(0, 0, 0, 0);
        }
        for (; i < e; i++) {
            g_rowptr[i] = run;
            run += g_cnt[i];
            g_cnt[i] = 0;
        }
    }
    if (t == 1023) g_rowptr[Nn] = sm[1023];
}

__global__ void k_scatter(const int* __restrict__ ei, int E, int Nn) {
    for (int e = blockIdx.x * blockDim.x + threadIdx.x; e < E; e += gridDim.x * blockDim.x) {
        int ss = ei[e];
        int dd = ei[E + e];
        if ((unsigned)dd < (unsigned)Nn) {
            int pos = g_rowptr[dd] + atomicAdd(&g_cnt[dd], 1);
            g_col[pos] = ss;
        }
    }
}

// ---------------- GEMM: C[M,BN] = A[M,K] @ B[K,BN], optional bias/act, optional fused s/d ----------------
template <int BN, int TN, int ACT, bool SD>
__global__ void __launch_bounds__(256, 3) k_gemm(const float* __restrict__ A,
                                                 const float* __restrict__ B,
                                                 const float* __restrict__ bias,
                                                 float* __restrict__ C,
                                                 const float* __restrict__ av_s,
                                                 const float* __restrict__ av_d,
                                                 int M, int K) {
    constexpr int BM = 128, BK = 32, TM = 8;
    constexpr int TX = BN / TN;                 // 16
    __shared__ float Ast[BK][BM + 4];
    __shared__ float Bs[BK][BN + 2];
    int tid = threadIdx.x;
    int tx = tid % TX, ty = tid / TX;
    int row0 = blockIdx.x * BM;

    float acc[TM][TN];
#pragma unroll
    for (int r = 0; r < TM; r++)
#pragma unroll
        for (int c = 0; c < TN; c++) acc[r][c] = 0.f;

    for (int k0 = 0; k0 < K; k0 += BK) {
        for (int i = tid; i < BM * (BK / 4); i += 256) {
            int r = i >> 3;
            int c4 = i & 7;
            int gr = row0 + r;
            float4 v = make_float4(0.f, 0.f, 0.f, 0.f);
            if (gr < M) v = *(const float4*)&A[(size_t)gr * K + k0 + (c4 << 2)];
            Ast[(c4 << 2) + 0][r] = v.x;
            Ast[(c4 << 2) + 1][r] = v.y;
            Ast[(c4 << 2) + 2][r] = v.z;
            Ast[(c4 << 2) + 3][r] = v.w;
        }
        for (int i = tid; i < BK * (BN / 4); i += 256) {
            int r = i / (BN / 4);
            int c4 = i % (BN / 4);
            float4 v = *(const float4*)&B[(size_t)(k0 + r) * BN + (c4 << 2)];
            *(float2*)&Bs[r][(c4 << 2)]     = make_float2(v.x, v.y);
            *(float2*)&Bs[r][(c4 << 2) + 2] = make_float2(v.z, v.w);
        }
        __syncthreads();
#pragma unroll 8
        for (int kk = 0; kk < BK; kk++) {
            float4 a0 = *(const float4*)&Ast[kk][ty * TM];
            float4 a1 = *(const float4*)&Ast[kk][ty * TM + 4];
            float a[TM] = {a0.x, a0.y, a0.z, a0.w, a1.x, a1.y, a1.z, a1.w};
            float bb[TN];
#pragma unroll
            for (int c2 = 0; c2 < TN / 2; c2++) {
                float2 t = *(const float2*)&Bs[kk][tx * TN + c2 * 2];
                bb[c2 * 2]     = t.x;
                bb[c2 * 2 + 1] = t.y;
            }
#pragma unroll
            for (int r = 0; r < TM; r++)
#pragma unroll
                for (int c = 0; c < TN; c++) acc[r][c] += a[r] * bb[c];
        }
        __syncthreads();
    }

    if (SD) {
        float sp[TM], dp[TM];
#pragma unroll
        for (int r = 0; r < TM; r++) { sp[r] = 0.f; dp[r] = 0.f; }
#pragma unroll
        for (int c = 0; c < TN; c++) {
            int col = tx * TN + c;
            float asv = av_s[col];
            float adv = av_d[col];
#pragma unroll
            for (int r = 0; r < TM; r++) {
                sp[r] += acc[r][c] * asv;
                dp[r] += acc[r][c] * adv;
            }
        }
#pragma unroll
        for (int r = 0; r < TM; r++) {
#pragma unroll
            for (int off = 1; off < 16; off <<= 1) {
                sp[r] += __shfl_xor_sync(0xffffffffu, sp[r], off);
                dp[r] += __shfl_xor_sync(0xffffffffu, dp[r], off);
            }
            int gr = row0 + ty * TM + r;
            if (tx == 0 && gr < M) {
                g_s[gr] = sp[r];
                g_d[gr] = dp[r];
            }
        }
    }

#pragma unroll
    for (int r = 0; r < TM; r++) {
        int gr = row0 + ty * TM + r;
        if (gr < M) {
#pragma unroll
            for (int c = 0; c < TN; c++) {
                int col = tx * TN + c;
                float v = acc[r][c];
                if (bias) v += bias[col];
                if (ACT == 1) v = fmaxf(v, 0.f);
                if (ACT == 2) v = 1.f / (1.f + __expf(-v));
                C[(size_t)gr * BN + col] = v;
            }
        }
    }
}

// ---------------- GAT softmax-aggregate (warp/node; smem (s,col) cache; 4x gather) ----------------
__device__ __forceinline__ float lrelu(float x) { return x > 0.f ? x : 0.2f * x; }

#define DEG_CACHE 128

__global__ void __launch_bounds__(256) k_agg(const float* __restrict__ h,
                                             const float* __restrict__ bias,
                                             float* __restrict__ out, int Nn) {
    __shared__ float2 sbuf[8][DEG_CACHE];
    int warp = threadIdx.x >> 5;
    int lane = threadIdx.x & 31;
    int n = blockIdx.x * 8 + warp;
    if (n >= Nn) return;
    int beg = g_rowptr[n];
    int end = g_rowptr[n + 1];
    int deg = end - beg;
    float dn = g_d[n];
    float e_self = lrelu(g_s[n] + dn);
    bool cached = (deg <= DEG_CACHE);

    // ---- pass 1: max (and cache (s, col) when it fits) ----
    float m = e_self;
    if (cached) {
        for (int idx = lane; idx < deg; idx += 32) {
            int c = g_col[beg + idx];
            float s = g_s[c];
            sbuf[warp][idx] = make_float2(s, __int_as_float(c));
            m = fmaxf(m, lrelu(s + dn));
        }
    } else {
        for (int j = beg + lane; j < end; j += 32)
            m = fmaxf(m, lrelu(g_s[g_col[j]] + dn));
    }
#pragma unroll
    for (int off = 16; off; off >>= 1)
        m = fmaxf(m, __shfl_xor_sync(0xffffffffu, m, off));

    // ---- pass 2 ----
    float w_self = __expf(e_self - m);
    float p = (lane == 0) ? w_self : 0.f;
    bool act = lane < 24;
    float4 acc = make_float4(0.f, 0.f, 0.f, 0.f);
    if (act) {
        float4 hv = *(const float4*)&h[(size_t)n * 96 + (size_t)lane * 4];
        acc.x = w_self * hv.x; acc.y = w_self * hv.y;
        acc.z = w_self * hv.z; acc.w = w_self * hv.w;
    }

    if (cached) {
        for (int idx = lane; idx < deg; idx += 32) {
            float2 sc = sbuf[warp][idx];
            float w = __expf(lrelu(sc.x + dn) - m);
            p += w;
            sbuf[warp][idx].x = w;
        }
        __syncwarp();
        if (act) {
            const size_t lo = (size_t)lane * 4;
            int t = 0;
            for (; t + 4 <= deg; t += 4) {
                float2 cw0 = sbuf[warp][t];
                float2 cw1 = sbuf[warp][t + 1];
                float2 cw2 = sbuf[warp][t + 2];
                float2 cw3 = sbuf[warp][t + 3];
                float4 h0 = *(const float4*)&h[(size_t)__float_as_int(cw0.y) * 96 + lo];
                float4 h1 = *(const float4*)&h[(size_t)__float_as_int(cw1.y) * 96 + lo];
                float4 h2 = *(const float4*)&h[(size_t)__float_as_int(cw2.y) * 96 + lo];
                float4 h3 = *(const float4*)&h[(size_t)__float_as_int(cw3.y) * 96 + lo];
                acc.x += cw0.x * h0.x; acc.y += cw0.x * h0.y; acc.z += cw0.x * h0.z; acc.w += cw0.x * h0.w;
                acc.x += cw1.x * h1.x; acc.y += cw1.x * h1.y; acc.z += cw1.x * h1.z; acc.w += cw1.x * h1.w;
                acc.x += cw2.x * h2.x; acc.y += cw2.x * h2.y; acc.z += cw2.x * h2.z; acc.w += cw2.x * h2.w;
                acc.x += cw3.x * h3.x; acc.y += cw3.x * h3.y; acc.z += cw3.x * h3.z; acc.w += cw3.x * h3.w;
            }
            for (; t < deg; t++) {
                float2 cw = sbuf[warp][t];
                float4 hv = *(const float4*)&h[(size_t)__float_as_int(cw.y) * 96 + lo];
                acc.x += cw.x * hv.x; acc.y += cw.x * hv.y;
                acc.z += cw.x * hv.z; acc.w += cw.x * hv.w;
            }
        }
        __syncwarp();
    } else {
        for (int j0 = beg; j0 < end; j0 += 32) {
            int j = j0 + lane;
            int c = 0; float w = 0.f;
            if (j < end) {
                c = g_col[j];
                w = __expf(lrelu(g_s[c] + dn) - m);
                p += w;
            }
            sbuf[warp][lane] = make_float2(w, __int_as_float(c));
            __syncwarp();
            int cnt = end - j0; if (cnt > 32) cnt = 32;
            if (act) {
                const size_t lo = (size_t)lane * 4;
                int t = 0;
                for (; t + 4 <= cnt; t += 4) {
                    float2 cw0 = sbuf[warp][t];
                    float2 cw1 = sbuf[warp][t + 1];
                    float2 cw2 = sbuf[warp][t + 2];
                    float2 cw3 = sbuf[warp][t + 3];
                    float4 h0 = *(const float4*)&h[(size_t)__float_as_int(cw0.y) * 96 + lo];
                    float4 h1 = *(const float4*)&h[(size_t)__float_as_int(cw1.y) * 96 + lo];
                    float4 h2 = *(const float4*)&h[(size_t)__float_as_int(cw2.y) * 96 + lo];
                    float4 h3 = *(const float4*)&h[(size_t)__float_as_int(cw3.y) * 96 + lo];
                    acc.x += cw0.x * h0.x; acc.y += cw0.x * h0.y; acc.z += cw0.x * h0.z; acc.w += cw0.x * h0.w;
                    acc.x += cw1.x * h1.x; acc.y += cw1.x * h1.y; acc.z += cw1.x * h1.z; acc.w += cw1.x * h1.w;
                    acc.x += cw2.x * h2.x; acc.y += cw2.x * h2.y; acc.z += cw2.x * h2.z; acc.w += cw2.x * h2.w;
                    acc.x += cw3.x * h3.x; acc.y += cw3.x * h3.y; acc.z += cw3.x * h3.z; acc.w += cw3.x * h3.w;
                }
                for (; t < cnt; t++) {
                    float2 cw = sbuf[warp][t];
                    float4 hv = *(const float4*)&h[(size_t)__float_as_int(cw.y) * 96 + lo];
                    acc.x += cw.x * hv.x; acc.y += cw.x * hv.y;
                    acc.z += cw.x * hv.z; acc.w += cw.x * hv.w;
                }
            }
            __syncwarp();
        }
    }

#pragma unroll
    for (int off = 16; off; off >>= 1)
        p += __shfl_xor_sync(0xffffffffu, p, off);

    float scale = 1.f / (fmaxf(p, 1e-16f) * (float)(deg + 1));
    if (act) {
        const float4 bv = *(const float4*)&bias[(size_t)lane * 4];
        float4 o4;
        o4.x = acc.x * scale + bv.x;
        o4.y = acc.y * scale + bv.y;
        o4.z = acc.z * scale + bv.z;
        o4.w = acc.w * scale + bv.w;
        *(float4*)&out[(size_t)n * 96 + (size_t)lane * 4] = o4;
    }
}

// ---------------- faithful view(3,N,32).sum(0) [+relu] ----------------
__global__ void k_reshape(const float* __restrict__ src, float* __restrict__ dst,
                          int Nn, int doRelu) {
    int t = blockIdx.x * blockDim.x + threadIdx.x;
    int tot = Nn * 32;
    if (t >= tot) return;
    float v = src[t] + src[t + tot] + src[t + 2 * tot];
    if (doRelu) v = fmaxf(v, 0.f);
    dst[t] = v;
}

// ---------------- launch ----------------
extern "C" void kernel_launch(void* const* d_in, const int* in_sizes, int n_in,
                              void* d_out, int out_size) {
    const float* x   = (const float*)d_in[0];
    const int*   ei  = (const int*)d_in[1];
    const float* W1  = (const float*)d_in[2];
    const float* as1 = (const float*)d_in[3];
    const float* ad1 = (const float*)d_in[4];
    const float* b1  = (const float*)d_in[5];
    const float* W2  = (const float*)d_in[6];
    const float* as2 = (const float*)d_in[7];
    const float* ad2 = (const float*)d_in[8];
    const float* b2  = (const float*)d_in[9];
    const float* Wl1 = (const float*)d_in[12];
    const float* bl1 = (const float*)d_in[13];
    const float* Wl2 = (const float*)d_in[14];
    const float* bl2 = (const float*)d_in[15];
    float* out = (float*)d_out;

    int Nn = in_sizes[0] / 128;
    int E  = in_sizes[1] / 2;
    if (Nn > N_MAX) Nn = N_MAX;
    if (E  > E_MAX) E  = E_MAX;

    float *p_h, *p_out, *p_y;
    cudaGetSymbolAddress((void**)&p_h,   g_h);
    cudaGetSymbolAddress((void**)&p_out, g_out);
    cudaGetSymbolAddress((void**)&p_y,   g_y);

    int gb = (Nn + 127) / 128;
    int wb = (Nn + 7) / 8;
    int rb = (Nn * 32 + 255) / 256;

    // ---- CSR build ----
    k_hist<<<1024, 256>>>(ei, E, Nn);                      // 1
    k_scan<<<1, 1024>>>(Nn);                               // 2
    k_scatter<<<1024, 256>>>(ei, E, Nn);                   // 3

    // ---- layer 1 (gemm computes h AND s/d) ----
    k_gemm<96, 6, 0, true><<<gb, 256>>>(x, W1, nullptr, p_h, as1, ad1, Nn, 128);  // 4 (profiled)
    k_agg<<<wb, 256>>>(p_h, b1, p_out, Nn);                // 5
    k_reshape<<<rb, 256>>>(p_out, p_y, Nn, 1);             // 6

    // ---- layer 2 ----
    k_gemm<96, 6, 0, true><<<gb, 256>>>(p_y, W2, nullptr, p_h, as2, ad2, Nn, 32);
    k_agg<<<wb, 256>>>(p_h, b2, p_out, Nn);
    k_reshape<<<rb, 256>>>(p_out, p_y, Nn, 0);

    // ---- MLP head ----
    k_gemm<96, 6, 1, false><<<gb, 256>>>(p_y, Wl1, bl1, p_h, nullptr, nullptr, Nn, 32);
    k_gemm<32, 2, 2, false><<<gb, 256>>>(p_h, Wl2, bl2, out, nullptr, nullptr, Nn, 96);

    // restore invariant: g_cnt == 0 for next call
    k_zero_cnt<<<(Nn + 255) / 256, 256>>>(Nn);

    (void)n_in; (void)out_size;
}